// round 7
// baseline (speedup 1.0000x reference)
#include <cuda_runtime.h>

#define LSEQ 65536
#define NB 32
#define NC 16
#define KW 8
#define THRV 0.25f
#define BETA 15.0f
#define XSC 20.0f

#define TILE_STRIDE 36                 // 32 steps + carry slot; rows 16B-aligned
#define WARP_TILE (32 * TILE_STRIDE)   // 1152 floats per warp tile
#define SMEM_FLOATS (16 * WARP_TILE)
#define SMEM_BYTES (SMEM_FLOATS * 4)   // 73728 -> 2 blocks/SM

typedef unsigned long long u64;

__device__ __forceinline__ float softplusf(float x) {
    return (x > 0.f) ? (x + log1pf(expf(-x))) : log1pf(expf(x));
}
__device__ __forceinline__ u64 pack2(float lo, float hi) {
    u64 r; asm("mov.b64 %0, {%1, %2};" : "=l"(r) : "f"(lo), "f"(hi)); return r;
}
__device__ __forceinline__ void unpack2(u64 v, float& lo, float& hi) {
    asm("mov.b64 {%0, %1}, %2;" : "=f"(lo), "=f"(hi) : "l"(v));
}
__device__ __forceinline__ u64 mul2(u64 a, u64 b) {
    u64 d; asm("mul.rn.f32x2 %0, %1, %2;" : "=l"(d) : "l"(a), "l"(b)); return d;
}
__device__ __forceinline__ u64 fma2(u64 a, u64 b, u64 c) {
    u64 d; asm("fma.rn.f32x2 %0, %1, %2, %3;" : "=l"(d) : "l"(a), "l"(b), "l"(c)); return d;
}

// 256 blocks x 512 threads (16 warps, 2 blocks/SM). block=(b, eighth of L);
// warp w = channel. Lane owns a 256-step chunk, warmed up 48 steps from v=0.
// Conv runs on the packed f32x2 pipe: steps (t,t+1) computed together using a
// window of overlapping packed pairs P[m]=(x[m],x[m+1]); bitwise == scalar.
// Only z staged in smem (stride 36, STS.128). s = (z>=0); I reconstructed in
// the drain from z + carry (tile col 32). Logits fused (256 threads, float4).
__global__ __launch_bounds__(512, 2) void snn_fused(
    const float* __restrict__ x,
    const float* __restrict__ wa, const float* __restrict__ wb,
    const float* __restrict__ rta, const float* __restrict__ rtb,
    const float* __restrict__ rga, const float* __restrict__ rgb,
    float* __restrict__ outI, float* __restrict__ outZ,
    float* __restrict__ outS, float* __restrict__ outL)
{
    extern __shared__ float smem[];
    float* tZ = smem;                               // [16][32][36]

    const int b = blockIdx.x >> 3;
    const int eighth = blockIdx.x & 7;
    const int tid = threadIdx.x;
    const int w = tid >> 5;            // channel 0..15
    const int lane = tid & 31;
    const int fidx = w & 7;
    const int isB = w >> 3;

    const float* wrow = (isB ? wb : wa) + fidx * KW;
    const float rt = (isB ? rtb : rta)[fidx];
    const float rg = (isB ? rgb : rga)[0];

    float wo[KW];
    float nsq = 0.f;
#pragma unroll
    for (int k = 0; k < KW; k++) { wo[k] = wrow[k]; nsq = fmaf(wo[k], wo[k], nsq); }
    float norm = sqrtf(nsq);
    if (norm < 1e-8f) norm = 1e-8f;
    const float g = softplusf(rg) + 1e-4f;

    const float alpha = expf(-1.0f / (softplusf(rt) + 1e-4f));
    const float oma = 1.0f - alpha;
    const float inv_oma = 1.0f / oma;
    const float invB = 1.0f / BETA;
    const float nBT = -BETA * THRV;

    const float scale = g * XSC / norm * oma;   // conv directly yields (1-a)*I
#pragma unroll
    for (int k = 0; k < KW; k++) wo[k] *= scale;
    u64 w2[KW];
#pragma unroll
    for (int k = 0; k < KW; k++) w2[k] = pack2(wo[k], wo[k]);

    const float* xr = x + ((size_t)(b * 2 + isB) << 16);
    const int p0i = eighth * 8192 + lane * 256;
    const int warm = (p0i == 0) ? 0 : 48;
    int lcur = p0i - warm;

    // scalar window for warmup: xw[0..7] = x[l-8 .. l-1]
    float xw[12];
    if (lcur >= 8) {
        float4 a4 = *(const float4*)(xr + lcur - 8);
        float4 b4 = *(const float4*)(xr + lcur - 4);
        xw[0] = a4.x; xw[1] = a4.y; xw[2] = a4.z; xw[3] = a4.w;
        xw[4] = b4.x; xw[5] = b4.y; xw[6] = b4.z; xw[7] = b4.w;
    } else {
#pragma unroll
        for (int k = 0; k < 8; k++) xw[k] = 0.f;
    }

    float vp = 0.f;   // pre-reset membrane of previous step

    // ---- warmup (0 or 48 steps), scalar, no emission ----
    for (int gg = 0; gg < (warm >> 2); ++gg) {
        float4 xv = *(const float4*)(xr + lcur);
        xw[8] = xv.x; xw[9] = xv.y; xw[10] = xv.z; xw[11] = xv.w;
#pragma unroll
        for (int k = 0; k < 4; k++) {
            float I = 0.f;
#pragma unroll
            for (int j = 0; j < 8; j++) I = fmaf(wo[j], xw[k + 1 + j], I);
            float cand = fmaf(alpha, vp, I);
            vp = (vp >= THRV) ? I : cand;
        }
#pragma unroll
        for (int j = 0; j < 8; j++) xw[j] = xw[j + 4];
        lcur += 4;
    }

    // prime packed pair window: P[i] = (x[t-7+i], x[t-6+i]) for i=0..5, t=lcur
    u64 p0 = pack2(xw[1], xw[2]);
    u64 p1 = pack2(xw[2], xw[3]);
    u64 p2 = pack2(xw[3], xw[4]);
    u64 p3 = pack2(xw[4], xw[5]);
    u64 p4 = pack2(xw[5], xw[6]);
    u64 p5 = pack2(xw[6], xw[7]);
    float xprev = xw[7];

    float* mtZ = tZ + w * WARP_TILE;
    float* rowZ = mtZ + lane * TILE_STRIDE;
    const size_t seqoff = ((size_t)(b * NC + w)) << 16;
    const int rsub = lane >> 3;          // 0..3
    const int cq = (lane & 7) * 4;       // 0,4,...,28

    for (int ph = 0; ph < 8; ++ph) {
        rowZ[32] = (vp >= THRV) ? 0.f : vp;   // carry: post-reset v at phase entry

        // 4-step packed group
        auto group = [&](float4 xv, int idx0) {
            u64 p6 = pack2(xprev, xv.x);
            u64 p7 = pack2(xv.x, xv.y);
            u64 p8 = pack2(xv.y, xv.z);
            u64 p9 = pack2(xv.z, xv.w);
            u64 a0 = mul2(w2[0], p0);
            a0 = fma2(w2[1], p1, a0); a0 = fma2(w2[2], p2, a0);
            a0 = fma2(w2[3], p3, a0); a0 = fma2(w2[4], p4, a0);
            a0 = fma2(w2[5], p5, a0); a0 = fma2(w2[6], p6, a0);
            a0 = fma2(w2[7], p7, a0);
            u64 a1 = mul2(w2[0], p2);
            a1 = fma2(w2[1], p3, a1); a1 = fma2(w2[2], p4, a1);
            a1 = fma2(w2[3], p5, a1); a1 = fma2(w2[4], p6, a1);
            a1 = fma2(w2[5], p7, a1); a1 = fma2(w2[6], p8, a1);
            a1 = fma2(w2[7], p9, a1);
            float I0, I1, I2, I3;
            unpack2(a0, I0, I1);
            unpack2(a1, I2, I3);
            float c, z0, z1, z2, z3;
            c = fmaf(alpha, vp, I0); vp = (vp >= THRV) ? I0 : c; z0 = fmaf(BETA, vp, nBT);
            c = fmaf(alpha, vp, I1); vp = (vp >= THRV) ? I1 : c; z1 = fmaf(BETA, vp, nBT);
            c = fmaf(alpha, vp, I2); vp = (vp >= THRV) ? I2 : c; z2 = fmaf(BETA, vp, nBT);
            c = fmaf(alpha, vp, I3); vp = (vp >= THRV) ? I3 : c; z3 = fmaf(BETA, vp, nBT);
            *(float4*)(rowZ + idx0) = make_float4(z0, z1, z2, z3);
            p0 = p4; p1 = p5; p2 = p6; p3 = p7; p4 = p8; p5 = p9;
            xprev = xv.w;
        };

#pragma unroll
        for (int sp = 0; sp < 4; ++sp) {
            float4 xv0 = *(const float4*)(xr + lcur);
            float4 xv1 = *(const float4*)(xr + lcur + 4);
            group(xv0, sp * 8);
            group(xv1, sp * 8 + 4);
            lcur += 8;
        }
        __syncthreads();

        // ---- warp-local drain: I,z,s from z tile; LDS.128 + STG.128 ----
        const size_t lbase = (size_t)(eighth * 8192 + ph * 32);
#pragma unroll
        for (int it = 0; it < 8; ++it) {
            const int r = it * 4 + rsub;
            const float* rw = mtZ + r * TILE_STRIDE;
            float4 z4 = *(const float4*)(rw + cq);
            float vprev;
            if (cq == 0) {
                vprev = rw[32];                       // carry: already post-reset
            } else {
                float zp = rw[cq - 1];
                vprev = (zp >= 0.f) ? 0.f : fmaf(zp, invB, THRV);
            }
            float vp0 = fmaf(z4.x, invB, THRV);
            float vp1 = fmaf(z4.y, invB, THRV);
            float vp2 = fmaf(z4.z, invB, THRV);
            float vp3 = fmaf(z4.w, invB, THRV);
            float4 vs;
            vs.x = (z4.x >= 0.f) ? 1.f : 0.f;
            vs.y = (z4.y >= 0.f) ? 1.f : 0.f;
            vs.z = (z4.z >= 0.f) ? 1.f : 0.f;
            vs.w = (z4.w >= 0.f) ? 1.f : 0.f;
            float4 vi;
            vi.x = (vp0 - alpha * vprev) * inv_oma;
            vi.y = (vp1 - alpha * ((z4.x >= 0.f) ? 0.f : vp0)) * inv_oma;
            vi.z = (vp2 - alpha * ((z4.y >= 0.f) ? 0.f : vp1)) * inv_oma;
            vi.w = (vp3 - alpha * ((z4.z >= 0.f) ? 0.f : vp2)) * inv_oma;
            const size_t gi = seqoff + lbase + (size_t)r * 256 + cq;
            __stcs((float4*)(outI + gi), vi);
            __stcs((float4*)(outZ + gi), z4);
            __stcs((float4*)(outS + gi), vs);
        }

        // ---- fused logits: max over 16 channels, 256 threads, float4 ----
        if (tid < 256) {
            const int j = tid >> 3;             // chunk row 0..31
            const int q = (tid & 7) * 4;        // step quad
            const float* p = tZ + j * TILE_STRIDE + q;
            float4 m = *(const float4*)p;
#pragma unroll
            for (int c2 = 1; c2 < 16; ++c2) {
                p += WARP_TILE;
                float4 t4 = *(const float4*)p;
                m.x = fmaxf(m.x, t4.x); m.y = fmaxf(m.y, t4.y);
                m.z = fmaxf(m.z, t4.z); m.w = fmaxf(m.w, t4.w);
            }
            const size_t gl = (((size_t)b) << 16)
                            + (size_t)(eighth * 8192 + j * 256 + ph * 32 + q);
            __stcs((float4*)(outL + gl), m);
        }
        __syncthreads();
    }
}

extern "C" void kernel_launch(void* const* d_in, const int* in_sizes, int n_in,
                              void* d_out, int out_size)
{
    const float* x   = (const float*)d_in[0];
    const float* wa  = (const float*)d_in[1];
    const float* wb  = (const float*)d_in[2];
    const float* rta = (const float*)d_in[3];
    const float* rtb = (const float*)d_in[4];
    const float* rga = (const float*)d_in[5];
    const float* rgb = (const float*)d_in[6];

    float* out = (float*)d_out;
    const size_t plane = (size_t)NB * NC * LSEQ;   // 33554432
    float* outI = out;
    float* outZ = out + plane;
    float* outS = out + 2 * plane;
    float* outL = out + 3 * plane;

    cudaFuncSetAttribute(snn_fused, cudaFuncAttributeMaxDynamicSharedMemorySize, SMEM_BYTES);
    snn_fused<<<256, 512, SMEM_BYTES>>>(x, wa, wb, rta, rtb, rga, rgb,
                                        outI, outZ, outS, outL);
}